// round 8
// baseline (speedup 1.0000x reference)
#include <cuda_runtime.h>
#include <math.h>
#include <stdint.h>

#define BATCH   2
#define CIN     512
#define NSEQ    2048
#define HEADS   16
#define DHEAD   64
#define HDIM    1024           // HEADS*DHEAD
#define O3      3072           // 3*HDIM
#define ATT_SCALE 8.0f

// Scratch (device globals: allocation-free scratch per harness rules)
__device__ float g_qkv[BATCH * O3 * NSEQ];     // [b][o][n], q/k normalized in place
__device__ float g_ao [BATCH * HDIM * NSEQ];   // attention output [b][c][n]

// ===========================================================================
// tf32 helpers (baseline PTX, valid on plain sm_103 — no 'a' features)
// ===========================================================================
__device__ __forceinline__ float to_tf32(float x) {
    uint32_t u;
    asm("cvt.rna.tf32.f32 %0, %1;" : "=r"(u) : "f"(x));
    return __uint_as_float(u);
}

// D(16x8) += A(16x8 row) * B(8x8 col), tf32 inputs, fp32 accum
// Proven fragment mapping (round 5/6):
//   a = [A(g,t), A(g+8,t), A(g,t+4), A(g+8,t+4)]   g=lane>>2, t=lane&3
//   b = [B(t,g), B(t+4,g)]                          (B indexed (k,n))
//   d = [D(g,2t), D(g,2t+1), D(g+8,2t), D(g+8,2t+1)]
__device__ __forceinline__ void mma_tf32(float* d, const float4& a, const float2& b) {
    asm volatile(
        "mma.sync.aligned.m16n8k8.row.col.f32.tf32.tf32.f32 "
        "{%0,%1,%2,%3}, {%4,%5,%6,%7}, {%8,%9}, {%0,%1,%2,%3};"
        : "+f"(d[0]), "+f"(d[1]), "+f"(d[2]), "+f"(d[3])
        : "r"(__float_as_uint(a.x)), "r"(__float_as_uint(a.y)),
          "r"(__float_as_uint(a.z)), "r"(__float_as_uint(a.w)),
          "r"(__float_as_uint(b.x)), "r"(__float_as_uint(b.y)));
}

// ===========================================================================
// tf32 mma.sync GEMM v2: Out[b][m][n] = sum_k W[m][k] * X[b][k][n] (+ bias[m])
// CTA tile 128m x 64n, 8 warps as 4(m) x 2(n), warp tile 32m x 32n.
// K-chunk 32, DOUBLE-BUFFERED smem, register prefetch, ONE sync per chunk.
// Fragment-permuted smem: A frag f=mt*4+kt (128 floats, LDS.128),
//                         B frag f=nt*4+kt (64 floats, LDS.64). Conflict-free.
// Smem: 2 * (4096 A + 2048 B) floats = 48KB dynamic.
// ===========================================================================
#define GT_SMEM_BYTES (12288 * 4)

__global__ __launch_bounds__(256, 2)
void tf32_gemm_kernel(const float* __restrict__ W,   // [M][K]
                      const float* __restrict__ X,   // [b][K][N]
                      float* __restrict__ Out,       // [b][M][N]
                      const float* __restrict__ bias,
                      int M, int K, int N)
{
    extern __shared__ float gs[];   // [0,8192) A bufs, [8192,12288) B bufs

    const int tid  = threadIdx.x;
    const int wid  = tid >> 5;
    const int lane = tid & 31;
    const int g = lane >> 2;
    const int t = lane & 3;
    const int wm = wid >> 1;       // 0..3
    const int wn = wid & 1;        // 0..1

    const int n0 = blockIdx.x * 64;
    const int m0 = blockIdx.y * 128;
    const int b  = blockIdx.z;

    const float* Ab = W + (size_t)m0 * K;
    const float* Xb = X + (size_t)b * K * N + n0;

    float d[2][4][4];
    #pragma unroll
    for (int a = 0; a < 2; a++)
        #pragma unroll
        for (int j = 0; j < 4; j++)
            #pragma unroll
            for (int r = 0; r < 4; r++) d[a][j][r] = 0.0f;

    // per-warp staged fragments (f = wid*4 + i)
    const int fmt = (wid * 4) >> 2;          // == wid (A: mt base), (B: nt base)
    float4 av[4];
    float2 bv[4];

    // ---- prologue: load + publish chunk 0
    #pragma unroll
    for (int i = 0; i < 4; i++) {
        const int kt = i;                    // f = wid*4+i -> mt = wid, kt = i
        const float* ap = Ab + (size_t)(fmt * 16 + g) * K + (kt * 8 + t);
        av[i].x = to_tf32(ap[0]);
        av[i].y = to_tf32(ap[(size_t)8 * K]);
        av[i].z = to_tf32(ap[4]);
        av[i].w = to_tf32(ap[(size_t)8 * K + 4]);
        const float* bp = Xb + (size_t)(kt * 8 + t) * N + (fmt * 8 + g);
        bv[i].x = to_tf32(bp[0]);
        bv[i].y = to_tf32(bp[(size_t)4 * N]);
    }
    #pragma unroll
    for (int i = 0; i < 4; i++) {
        *(float4*)(gs + (wid * 4 + i) * 128 + lane * 4)        = av[i];
        *(float2*)(gs + 8192 + (wid * 4 + i) * 64 + lane * 2)  = bv[i];
    }
    __syncthreads();

    const int nch = K >> 5;
    for (int c = 0; c < nch; c++) {
        const int cur = c & 1;

        // ---- prefetch chunk c+1 into registers (overlaps with MMAs below)
        if (c + 1 < nch) {
            const int k0 = (c + 1) << 5;
            #pragma unroll
            for (int i = 0; i < 4; i++) {
                const int kt = i;
                const float* ap = Ab + (size_t)(fmt * 16 + g) * K + (k0 + kt * 8 + t);
                av[i].x = to_tf32(ap[0]);
                av[i].y = to_tf32(ap[(size_t)8 * K]);
                av[i].z = to_tf32(ap[4]);
                av[i].w = to_tf32(ap[(size_t)8 * K + 4]);
                const float* bp = Xb + (size_t)(k0 + kt * 8 + t) * N + (fmt * 8 + g);
                bv[i].x = to_tf32(bp[0]);
                bv[i].y = to_tf32(bp[(size_t)4 * N]);
            }
        }

        // ---- compute chunk c from buffer cur
        const float* Aw = gs + cur * 4096;
        const float* Bw = gs + 8192 + cur * 2048;
        #pragma unroll
        for (int kt = 0; kt < 4; kt++) {
            float4 afr[2];
            afr[0] = *(const float4*)(Aw + ((wm * 2    ) * 4 + kt) * 128 + lane * 4);
            afr[1] = *(const float4*)(Aw + ((wm * 2 + 1) * 4 + kt) * 128 + lane * 4);
            float2 bfr[4];
            #pragma unroll
            for (int j = 0; j < 4; j++)
                bfr[j] = *(const float2*)(Bw + ((wn * 4 + j) * 4 + kt) * 64 + lane * 2);
            #pragma unroll
            for (int a = 0; a < 2; a++)
                #pragma unroll
                for (int j = 0; j < 4; j++)
                    mma_tf32(d[a][j], afr[a], bfr[j]);
        }

        // ---- publish chunk c+1 into the other buffer, one sync
        if (c + 1 < nch) {
            float* An = gs + (cur ^ 1) * 4096;
            float* Bn = gs + 8192 + (cur ^ 1) * 2048;
            #pragma unroll
            for (int i = 0; i < 4; i++) {
                *(float4*)(An + (wid * 4 + i) * 128 + lane * 4) = av[i];
                *(float2*)(Bn + (wid * 4 + i) * 64 + lane * 2)  = bv[i];
            }
            __syncthreads();
        }
    }

    // ---- epilogue: coalesced float2 stores (+bias)
    float* Ob = Out + (size_t)b * M * N;
    #pragma unroll
    for (int a = 0; a < 2; a++) {
        const int row = m0 + wm * 32 + a * 16 + g;
        const float b1 = bias ? bias[row]     : 0.0f;
        const float b2 = bias ? bias[row + 8] : 0.0f;
        #pragma unroll
        for (int j = 0; j < 4; j++) {
            const int col = n0 + wn * 32 + j * 8 + t * 2;
            float2 v0; v0.x = d[a][j][0] + b1; v0.y = d[a][j][1] + b1;
            float2 v1; v1.x = d[a][j][2] + b2; v1.y = d[a][j][3] + b2;
            *(float2*)(Ob + (size_t)row * N + col)       = v0;
            *(float2*)(Ob + (size_t)(row + 8) * N + col) = v1;
        }
    }
}

// ---------------------------------------------------------------------------
// L2 normalization of q,k over head-dim (in place in g_qkv), applying scales.
// ---------------------------------------------------------------------------
__global__ __launch_bounds__(256)
void l2norm_kernel(float* __restrict__ qkv,
                   const float* __restrict__ qs,
                   const float* __restrict__ ks)
{
    const int n  = blockIdx.x * 256 + threadIdx.x;
    const int h  = blockIdx.y;
    const int bw = blockIdx.z;
    const int b  = bw >> 1;
    const int w  = bw & 1;
    const float* sc = w ? ks : qs;

    float* base = qkv + ((size_t)b * O3 + (size_t)w * HDIM + (size_t)h * DHEAD) * NSEQ + n;

    float ss = 0.0f;
    #pragma unroll
    for (int d = 0; d < DHEAD; d++) {
        float v = base[(size_t)d * NSEQ];
        ss += v * v;
    }
    float inv = 1.0f / fmaxf(sqrtf(ss), 1e-12f);
    #pragma unroll
    for (int d = 0; d < DHEAD; d++) {
        base[(size_t)d * NSEQ] = base[(size_t)d * NSEQ] * inv * sc[d];
    }
}

// ===========================================================================
// Flash attention v3, tf32 mma.sync, FIXED-MAX softmax.
// Cosine attention: q,k L2-normalized => logits s = 8*cos(q,k) in [-8, 8].
// So softmax uses exp(s - 8): no online max, no rescaling, no max shuffles.
// One CTA = 128 query rows of one (b,h); 8 warps; warp w owns rows w*16..+15.
// Smem: Kf[4096] / Vf[4096] fragment-permuted B-frags, Pf[8192] per-warp
// A-frag buffers. Pipeline: STS K; sync; LDG V; S-MMA+softmax+P-store;
//                           STS V; sync; LDG K(next); PV-MMA.
// ===========================================================================
#define ATT_SMEM_BYTES (16384 * 4)

__global__ __launch_bounds__(256, 2)
void attn_tc_kernel(const float* __restrict__ qkv, float* __restrict__ ao)
{
    extern __shared__ float smf[];
    float* Kf = smf;             // 4096
    float* Vf = smf + 4096;      // 4096
    float* Pf = smf + 8192;      // 8192

    const int tid  = threadIdx.x;
    const int wid  = tid >> 5;
    const int lane = tid & 31;
    const int g = lane >> 2;
    const int t = lane & 3;
    const int r0 = wid * 16;

    const int i0 = blockIdx.x * 128;
    const int h  = blockIdx.y;
    const int b  = blockIdx.z;

    const float* qb = qkv + ((size_t)b * O3 + (size_t)h * DHEAD) * NSEQ;
    const float* kb = qb + (size_t)HDIM * NSEQ;
    const float* vb = qb + (size_t)(2 * HDIM) * NSEQ;

    float* Pw = Pf + wid * 1024;

    // ---- Q fragments straight from gmem into registers (live whole kernel)
    float4 qf[8];
    #pragma unroll
    for (int kt = 0; kt < 8; kt++) {
        const float* qp = qb + (size_t)(kt * 8 + t) * NSEQ + i0 + r0 + g;
        qf[kt].x = to_tf32(qp[0] * ATT_SCALE);
        qf[kt].y = to_tf32(qp[8] * ATT_SCALE);
        qf[kt].z = to_tf32(qp[(size_t)4 * NSEQ] * ATT_SCALE);
        qf[kt].w = to_tf32(qp[(size_t)4 * NSEQ + 8] * ATT_SCALE);
    }

    // ---- preload K tile 0 into regs (warp w stages frags f = w*8+kt, nt=w)
    float2 kreg[8];
    #pragma unroll
    for (int i = 0; i < 8; i++) {
        const float* kp = kb + (size_t)(i * 8 + t) * NSEQ + (wid * 8 + g);
        kreg[i].x = kp[0];
        kreg[i].y = kp[(size_t)4 * NSEQ];
    }

    float lrow0 = 0.0f, lrow1 = 0.0f;
    float o[8][4];
    #pragma unroll
    for (int nt = 0; nt < 8; nt++)
        #pragma unroll
        for (int r = 0; r < 4; r++) o[nt][r] = 0.0f;

    for (int j0 = 0; j0 < NSEQ; j0 += 64) {
        // ---- publish K frags
        #pragma unroll
        for (int i = 0; i < 8; i++) {
            float2 v; v.x = to_tf32(kreg[i].x); v.y = to_tf32(kreg[i].y);
            *(float2*)(Kf + (wid * 8 + i) * 64 + lane * 2) = v;
        }
        __syncthreads();   // K ready; also clears prior-iter PV readers of Vf

        // ---- issue V loads (latency covered by S-MMA + softmax)
        float2 vreg[8];
        #pragma unroll
        for (int i = 0; i < 8; i++) {
            const float* vp = vb + (size_t)(wid * 8 + g) * NSEQ + j0 + i * 8 + t;
            vreg[i].x = vp[0];
            vreg[i].y = vp[4];
        }

        // ---- S = Q K^T  (B-frag = one LDS.64, conflict-free)
        float s[8][4];
        #pragma unroll
        for (int nt = 0; nt < 8; nt++)
            #pragma unroll
            for (int r = 0; r < 4; r++) s[nt][r] = 0.0f;

        #pragma unroll
        for (int kt = 0; kt < 8; kt++)
            #pragma unroll
            for (int nt = 0; nt < 8; nt++)
                mma_tf32(s[nt], qf[kt],
                         *(const float2*)(Kf + (nt * 8 + kt) * 64 + lane * 2));

        // ---- fixed-max softmax: P = exp(s - 8), logits bounded by 8
        float sum0 = 0.0f, sum1 = 0.0f;
        #pragma unroll
        for (int nt = 0; nt < 8; nt++) {
            float p0 = __expf(s[nt][0] - 8.0f);
            float p1 = __expf(s[nt][1] - 8.0f);
            float p2 = __expf(s[nt][2] - 8.0f);
            float p3 = __expf(s[nt][3] - 8.0f);
            sum0 += p0 + p1;
            sum1 += p2 + p3;
            const int c = 2 * t;
            const int base0 = nt * 128 + g * 16 + (c & 3) * 4 + ((c >= 4) ? 2 : 0);
            float2 e0; e0.x = to_tf32(p0); e0.y = to_tf32(p2);
            *(float2*)(Pw + base0) = e0;
            const int c1i = c + 1;
            const int base1 = nt * 128 + g * 16 + (c1i & 3) * 4 + ((c1i >= 4) ? 2 : 0);
            float2 e1; e1.x = to_tf32(p1); e1.y = to_tf32(p3);
            *(float2*)(Pw + base1) = e1;
        }
        sum0 += __shfl_xor_sync(0xffffffffu, sum0, 1);
        sum0 += __shfl_xor_sync(0xffffffffu, sum0, 2);
        sum1 += __shfl_xor_sync(0xffffffffu, sum1, 1);
        sum1 += __shfl_xor_sync(0xffffffffu, sum1, 2);
        lrow0 += sum0;
        lrow1 += sum1;

        // ---- publish V frags
        #pragma unroll
        for (int i = 0; i < 8; i++) {
            float2 v; v.x = to_tf32(vreg[i].x); v.y = to_tf32(vreg[i].y);
            *(float2*)(Vf + (wid * 8 + i) * 64 + lane * 2) = v;
        }
        __syncthreads();   // V ready; also makes this warp's P stores visible-ordered

        // ---- prefetch next K tile (latency covered by PV; s[] dead here)
        const int jn = (j0 + 64 < NSEQ) ? j0 + 64 : 0;
        #pragma unroll
        for (int i = 0; i < 8; i++) {
            const float* kp = kb + (size_t)(i * 8 + t) * NSEQ + jn + wid * 8 + g;
            kreg[i].x = kp[0];
            kreg[i].y = kp[(size_t)4 * NSEQ];
        }

        // ---- O += P V^T  (A-frag = LDS.128, B-frag = LDS.64, conflict-free)
        #pragma unroll
        for (int kt = 0; kt < 8; kt++) {
            float4 af = *(const float4*)(Pw + kt * 128 + lane * 4);
            #pragma unroll
            for (int nt = 0; nt < 8; nt++)
                mma_tf32(o[nt], af,
                         *(const float2*)(Vf + (nt * 8 + kt) * 64 + lane * 2));
        }
    }
    __syncthreads();

    // ---- normalize + transpose to [d][i] through smem, coalesced store
    const float inv0 = 1.0f / lrow0;
    const float inv1 = 1.0f / lrow1;
    float* Ts = smf;    // 64 x 132
    #pragma unroll
    for (int nt = 0; nt < 8; nt++) {
        Ts[(nt * 8 + 2 * t)     * 132 + r0 + g]     = o[nt][0] * inv0;
        Ts[(nt * 8 + 2 * t + 1) * 132 + r0 + g]     = o[nt][1] * inv0;
        Ts[(nt * 8 + 2 * t)     * 132 + r0 + g + 8] = o[nt][2] * inv1;
        Ts[(nt * 8 + 2 * t + 1) * 132 + r0 + g + 8] = o[nt][3] * inv1;
    }
    __syncthreads();

    float* aob = ao + ((size_t)b * HDIM + (size_t)h * DHEAD) * NSEQ;
    for (int e = tid; e < 64 * 128; e += 256) {
        int d = e >> 7, i = e & 127;
        aob[(size_t)d * NSEQ + i0 + i] = Ts[d * 132 + i];
    }
}

// ---------------------------------------------------------------------------
extern "C" void kernel_launch(void* const* d_in, const int* in_sizes, int n_in,
                              void* d_out, int out_size)
{
    const float* x       = (const float*)d_in[0];
    const float* Wqkv    = (const float*)d_in[1];
    const float* q_scale = (const float*)d_in[2];
    const float* k_scale = (const float*)d_in[3];
    const float* Wout    = (const float*)d_in[4];
    const float* bout    = (const float*)d_in[5];
    float*       out     = (float*)d_out;

    float *qkv = nullptr, *ao = nullptr;
    cudaGetSymbolAddress((void**)&qkv, g_qkv);
    cudaGetSymbolAddress((void**)&ao,  g_ao);

    cudaFuncSetAttribute(tf32_gemm_kernel,
                         cudaFuncAttributeMaxDynamicSharedMemorySize, GT_SMEM_BYTES);
    cudaFuncSetAttribute(attn_tc_kernel,
                         cudaFuncAttributeMaxDynamicSharedMemorySize, ATT_SMEM_BYTES);

    // 1) QKV projection (tf32 mma.sync, double-buffered): M=3072, K=512, N=2048
    tf32_gemm_kernel<<<dim3(NSEQ / 64, O3 / 128, BATCH), 256, GT_SMEM_BYTES>>>(
        Wqkv, x, qkv, nullptr, O3, CIN, NSEQ);

    // 2) l2-normalize q,k in place (+ learned per-dim scales)
    l2norm_kernel<<<dim3(NSEQ / 256, HEADS, BATCH * 2), 256>>>(
        qkv, q_scale, k_scale);

    // 3) flash attention (tf32 mma.sync, fixed-max softmax)
    attn_tc_kernel<<<dim3(NSEQ / 128, HEADS, BATCH), 256, ATT_SMEM_BYTES>>>(qkv, ao);

    // 4) output projection (tf32 mma.sync, double-buffered): M=512, K=1024, N=2048
    tf32_gemm_kernel<<<dim3(NSEQ / 64, CIN / 128, BATCH), 256, GT_SMEM_BYTES>>>(
        Wout, ao, out, bout, CIN, HDIM, NSEQ);
}

// round 11
// speedup vs baseline: 1.0642x; 1.0642x over previous
#include <cuda_runtime.h>
#include <math.h>
#include <stdint.h>

#define BATCH   2
#define CIN     512
#define NSEQ    2048
#define HEADS   16
#define DHEAD   64
#define HDIM    1024           // HEADS*DHEAD
#define O3      3072           // 3*HDIM
#define ATT_SCALE 8.0f

// Scratch (device globals: allocation-free scratch per harness rules)
__device__ float g_qkv[BATCH * O3 * NSEQ];     // [b][o][n], q/k normalized in place
__device__ float g_ao [BATCH * HDIM * NSEQ];   // attention output [b][c][n]

// ===========================================================================
// tf32 helpers (baseline PTX, valid on plain sm_103 — no 'a' features)
// ===========================================================================
__device__ __forceinline__ float to_tf32(float x) {
    uint32_t u;
    asm("cvt.rna.tf32.f32 %0, %1;" : "=r"(u) : "f"(x));
    return __uint_as_float(u);
}

// D(16x8) += A(16x8 row) * B(8x8 col), tf32 inputs, fp32 accum
// Proven fragment mapping (round 5/6):
//   a = [A(g,t), A(g+8,t), A(g,t+4), A(g+8,t+4)]   g=lane>>2, t=lane&3
//   b = [B(t,g), B(t+4,g)]                          (B indexed (k,n))
//   d = [D(g,2t), D(g,2t+1), D(g+8,2t), D(g+8,2t+1)]
__device__ __forceinline__ void mma_tf32(float* d, const float4& a, const float2& b) {
    asm volatile(
        "mma.sync.aligned.m16n8k8.row.col.f32.tf32.tf32.f32 "
        "{%0,%1,%2,%3}, {%4,%5,%6,%7}, {%8,%9}, {%0,%1,%2,%3};"
        : "+f"(d[0]), "+f"(d[1]), "+f"(d[2]), "+f"(d[3])
        : "r"(__float_as_uint(a.x)), "r"(__float_as_uint(a.y)),
          "r"(__float_as_uint(a.z)), "r"(__float_as_uint(a.w)),
          "r"(__float_as_uint(b.x)), "r"(__float_as_uint(b.y)));
}

// ===========================================================================
// tf32 mma.sync GEMM (exact round-5/7 proven version, 128x128 tile)
// ===========================================================================
__global__ __launch_bounds__(256, 2)
void tf32_gemm_kernel(const float* __restrict__ W,   // [M][K]
                      const float* __restrict__ X,   // [b][K][N]
                      float* __restrict__ Out,       // [b][M][N]
                      const float* __restrict__ bias,
                      int M, int K, int N)
{
    __shared__ float As[4096];
    __shared__ float Bs[4096];

    const int tid  = threadIdx.x;
    const int wid  = tid >> 5;
    const int lane = tid & 31;
    const int g = lane >> 2;
    const int t = lane & 3;
    const int wm = wid >> 1;
    const int wn = wid & 1;

    const int n0 = blockIdx.x * 128;
    const int m0 = blockIdx.y * 128;
    const int b  = blockIdx.z;

    const float* Ab = W + (size_t)m0 * K;
    const float* Xb = X + (size_t)b * K * N + n0;

    float d[2][8][4];
    #pragma unroll
    for (int a = 0; a < 2; a++)
        #pragma unroll
        for (int j = 0; j < 8; j++)
            #pragma unroll
            for (int r = 0; r < 4; r++) d[a][j][r] = 0.0f;

    const int nch = K >> 5;
    for (int c = 0; c < nch; c++) {
        const int k0 = c << 5;

        #pragma unroll
        for (int i = 0; i < 4; i++) {
            int f  = wid * 4 + i;
            int mt = f >> 2, kt = f & 3;
            const float* ap = Ab + (size_t)(mt * 16 + g) * K + (k0 + kt * 8 + t);
            float4 v;
            v.x = to_tf32(ap[0]);
            v.y = to_tf32(ap[(size_t)8 * K]);
            v.z = to_tf32(ap[4]);
            v.w = to_tf32(ap[(size_t)8 * K + 4]);
            *(float4*)(As + f * 128 + lane * 4) = v;
        }
        #pragma unroll
        for (int i = 0; i < 8; i++) {
            int f  = wid * 8 + i;
            int nt = f >> 2, kt = f & 3;
            const float* bp = Xb + (size_t)(k0 + kt * 8 + t) * N + (nt * 8 + g);
            float2 v;
            v.x = to_tf32(bp[0]);
            v.y = to_tf32(bp[(size_t)4 * N]);
            *(float2*)(Bs + f * 64 + lane * 2) = v;
        }
        __syncthreads();

        const float* Aw = As + (wm * 2) * 4 * 128;
        const float* Bw = Bs + (wn * 8) * 4 * 64;
        #pragma unroll
        for (int kt = 0; kt < 4; kt++) {
            float4 afr[2];
            afr[0] = *(const float4*)(Aw + (kt    ) * 128 + lane * 4);
            afr[1] = *(const float4*)(Aw + (kt + 4) * 128 + lane * 4);
            float2 bfr[8];
            #pragma unroll
            for (int j = 0; j < 8; j++)
                bfr[j] = *(const float2*)(Bw + (j * 4 + kt) * 64 + lane * 2);
            #pragma unroll
            for (int a = 0; a < 2; a++)
                #pragma unroll
                for (int j = 0; j < 8; j++)
                    mma_tf32(d[a][j], afr[a], bfr[j]);
        }
        __syncthreads();
    }

    float* Ob = Out + (size_t)b * M * N;
    #pragma unroll
    for (int a = 0; a < 2; a++) {
        const int row = m0 + wm * 32 + a * 16 + g;
        const float b1 = bias ? bias[row]     : 0.0f;
        const float b2 = bias ? bias[row + 8] : 0.0f;
        #pragma unroll
        for (int j = 0; j < 8; j++) {
            const int col = n0 + wn * 64 + j * 8 + t * 2;
            float2 v0; v0.x = d[a][j][0] + b1; v0.y = d[a][j][1] + b1;
            float2 v1; v1.x = d[a][j][2] + b2; v1.y = d[a][j][3] + b2;
            *(float2*)(Ob + (size_t)row * N + col)       = v0;
            *(float2*)(Ob + (size_t)(row + 8) * N + col) = v1;
        }
    }
}

// ---------------------------------------------------------------------------
// L2 normalization of q,k over head-dim (in place in g_qkv), applying scales.
// ---------------------------------------------------------------------------
__global__ __launch_bounds__(256)
void l2norm_kernel(float* __restrict__ qkv,
                   const float* __restrict__ qs,
                   const float* __restrict__ ks)
{
    const int n  = blockIdx.x * 256 + threadIdx.x;
    const int h  = blockIdx.y;
    const int bw = blockIdx.z;
    const int b  = bw >> 1;
    const int w  = bw & 1;
    const float* sc = w ? ks : qs;

    float* base = qkv + ((size_t)b * O3 + (size_t)w * HDIM + (size_t)h * DHEAD) * NSEQ + n;

    float ss = 0.0f;
    #pragma unroll
    for (int d = 0; d < DHEAD; d++) {
        float v = base[(size_t)d * NSEQ];
        ss += v * v;
    }
    float inv = 1.0f / fmaxf(sqrtf(ss), 1e-12f);
    #pragma unroll
    for (int d = 0; d < DHEAD; d++) {
        base[(size_t)d * NSEQ] = base[(size_t)d * NSEQ] * inv * sc[d];
    }
}

// ===========================================================================
// Flash attention v4: tf32 mma.sync, fixed-max softmax, PAIRED B-fragments.
// Cosine attention: logits bounded by 8 => exp(s - 8), no online max.
// One CTA = 128 query rows of one (b,h); 8 warps; warp w owns rows w*16..+15.
//
// Paired B-frag layout (K and V): pair p = nt*4 + ktp holds frags
// (nt, 2ktp) and (nt, 2ktp+1) interleaved per lane:
//   addr p*128 + lane*4 -> { f0.x, f0.y, f1.x, f1.y }
// One LDS.128 feeds two MMAs; one STS.128 publishes two frags.
// Pf: per-warp A-frag buffers (8 frags * 128 floats), read by LDS.128.
// Pipeline: STS K; sync; LDG V; S-MMA+softmax+P-store;
//           STS V; sync; LDG K(next); PV-MMA.
// ===========================================================================
#define ATT_SMEM_BYTES (16384 * 4)

__global__ __launch_bounds__(256, 2)
void attn_tc_kernel(const float* __restrict__ qkv, float* __restrict__ ao)
{
    extern __shared__ float smf[];
    float* Kf = smf;             // 4096 (32 pairs * 128)
    float* Vf = smf + 4096;      // 4096
    float* Pf = smf + 8192;      // 8192

    const int tid  = threadIdx.x;
    const int wid  = tid >> 5;
    const int lane = tid & 31;
    const int g = lane >> 2;
    const int t = lane & 3;
    const int r0 = wid * 16;

    const int i0 = blockIdx.x * 128;
    const int h  = blockIdx.y;
    const int b  = blockIdx.z;

    const float* qb = qkv + ((size_t)b * O3 + (size_t)h * DHEAD) * NSEQ;
    const float* kb = qb + (size_t)HDIM * NSEQ;
    const float* vb = qb + (size_t)(2 * HDIM) * NSEQ;

    float* Pw = Pf + wid * 1024;

    // ---- Q fragments straight from gmem into registers (live whole kernel)
    float4 qf[8];
    #pragma unroll
    for (int kt = 0; kt < 8; kt++) {
        const float* qp = qb + (size_t)(kt * 8 + t) * NSEQ + i0 + r0 + g;
        qf[kt].x = to_tf32(qp[0] * ATT_SCALE);
        qf[kt].y = to_tf32(qp[8] * ATT_SCALE);
        qf[kt].z = to_tf32(qp[(size_t)4 * NSEQ] * ATT_SCALE);
        qf[kt].w = to_tf32(qp[(size_t)4 * NSEQ + 8] * ATT_SCALE);
    }

    // ---- preload K tile 0 into regs (warp w stages frags nt=w, kt=0..7)
    float2 kreg[8];
    #pragma unroll
    for (int i = 0; i < 8; i++) {
        const float* kp = kb + (size_t)(i * 8 + t) * NSEQ + (wid * 8 + g);
        kreg[i].x = kp[0];
        kreg[i].y = kp[(size_t)4 * NSEQ];
    }

    float lrow0 = 0.0f, lrow1 = 0.0f;
    float o[8][4];
    #pragma unroll
    for (int nt = 0; nt < 8; nt++)
        #pragma unroll
        for (int r = 0; r < 4; r++) o[nt][r] = 0.0f;

    for (int j0 = 0; j0 < NSEQ; j0 += 64) {
        // ---- publish K frag-pairs: 4 STS.128 per warp
        #pragma unroll
        for (int p = 0; p < 4; p++) {
            float4 v;
            v.x = to_tf32(kreg[2 * p].x);     v.y = to_tf32(kreg[2 * p].y);
            v.z = to_tf32(kreg[2 * p + 1].x); v.w = to_tf32(kreg[2 * p + 1].y);
            *(float4*)(Kf + (wid * 4 + p) * 128 + lane * 4) = v;
        }
        __syncthreads();   // K ready; also clears prior-iter PV readers of Vf

        // ---- issue V loads (latency covered by S-MMA + softmax)
        float2 vreg[8];
        #pragma unroll
        for (int i = 0; i < 8; i++) {
            const float* vp = vb + (size_t)(wid * 8 + g) * NSEQ + j0 + i * 8 + t;
            vreg[i].x = vp[0];
            vreg[i].y = vp[4];
        }

        // ---- S = Q K^T  (one LDS.128 = two B-frags = two MMAs)
        float s[8][4];
        #pragma unroll
        for (int nt = 0; nt < 8; nt++)
            #pragma unroll
            for (int r = 0; r < 4; r++) s[nt][r] = 0.0f;

        #pragma unroll
        for (int ktp = 0; ktp < 4; ktp++) {
            #pragma unroll
            for (int nt = 0; nt < 8; nt++) {
                float4 kp4 = *(const float4*)(Kf + (nt * 4 + ktp) * 128 + lane * 4);
                float2 b0; b0.x = kp4.x; b0.y = kp4.y;
                float2 b1; b1.x = kp4.z; b1.y = kp4.w;
                mma_tf32(s[nt], qf[2 * ktp],     b0);
                mma_tf32(s[nt], qf[2 * ktp + 1], b1);
            }
        }

        // ---- fixed-max softmax: P = exp(s - 8), logits bounded by 8
        float sum0 = 0.0f, sum1 = 0.0f;
        #pragma unroll
        for (int nt = 0; nt < 8; nt++) {
            float p0 = __expf(s[nt][0] - 8.0f);
            float p1 = __expf(s[nt][1] - 8.0f);
            float p2 = __expf(s[nt][2] - 8.0f);
            float p3 = __expf(s[nt][3] - 8.0f);
            sum0 += p0 + p1;
            sum1 += p2 + p3;
            const int c = 2 * t;
            const int base0 = nt * 128 + g * 16 + (c & 3) * 4 + ((c >= 4) ? 2 : 0);
            float2 e0; e0.x = to_tf32(p0); e0.y = to_tf32(p2);
            *(float2*)(Pw + base0) = e0;
            const int c1i = c + 1;
            const int base1 = nt * 128 + g * 16 + (c1i & 3) * 4 + ((c1i >= 4) ? 2 : 0);
            float2 e1; e1.x = to_tf32(p1); e1.y = to_tf32(p3);
            *(float2*)(Pw + base1) = e1;
        }
        sum0 += __shfl_xor_sync(0xffffffffu, sum0, 1);
        sum0 += __shfl_xor_sync(0xffffffffu, sum0, 2);
        sum1 += __shfl_xor_sync(0xffffffffu, sum1, 1);
        sum1 += __shfl_xor_sync(0xffffffffu, sum1, 2);
        lrow0 += sum0;
        lrow1 += sum1;

        // ---- publish V frag-pairs: 4 STS.128 per warp
        #pragma unroll
        for (int p = 0; p < 4; p++) {
            float4 v;
            v.x = to_tf32(vreg[2 * p].x);     v.y = to_tf32(vreg[2 * p].y);
            v.z = to_tf32(vreg[2 * p + 1].x); v.w = to_tf32(vreg[2 * p + 1].y);
            *(float4*)(Vf + (wid * 4 + p) * 128 + lane * 4) = v;
        }
        __syncthreads();   // V ready; also makes this warp's P stores ordered

        // ---- prefetch next K tile (latency covered by PV; s[] dead here)
        const int jn = (j0 + 64 < NSEQ) ? j0 + 64 : 0;
        #pragma unroll
        for (int i = 0; i < 8; i++) {
            const float* kp = kb + (size_t)(i * 8 + t) * NSEQ + jn + wid * 8 + g;
            kreg[i].x = kp[0];
            kreg[i].y = kp[(size_t)4 * NSEQ];
        }

        // ---- O += P V^T  (A: LDS.128; B pair: one LDS.128 = two MMAs)
        #pragma unroll
        for (int ktp = 0; ktp < 4; ktp++) {
            float4 af0 = *(const float4*)(Pw + (2 * ktp)     * 128 + lane * 4);
            float4 af1 = *(const float4*)(Pw + (2 * ktp + 1) * 128 + lane * 4);
            #pragma unroll
            for (int nt = 0; nt < 8; nt++) {
                float4 vp4 = *(const float4*)(Vf + (nt * 4 + ktp) * 128 + lane * 4);
                float2 b0; b0.x = vp4.x; b0.y = vp4.y;
                float2 b1; b1.x = vp4.z; b1.y = vp4.w;
                mma_tf32(o[nt], af0, b0);
                mma_tf32(o[nt], af1, b1);
            }
        }
    }
    __syncthreads();

    // ---- normalize + transpose to [d][i] through smem, coalesced store
    const float inv0 = 1.0f / lrow0;
    const float inv1 = 1.0f / lrow1;
    float* Ts = smf;    // 64 x 132
    #pragma unroll
    for (int nt = 0; nt < 8; nt++) {
        Ts[(nt * 8 + 2 * t)     * 132 + r0 + g]     = o[nt][0] * inv0;
        Ts[(nt * 8 + 2 * t + 1) * 132 + r0 + g]     = o[nt][1] * inv0;
        Ts[(nt * 8 + 2 * t)     * 132 + r0 + g + 8] = o[nt][2] * inv1;
        Ts[(nt * 8 + 2 * t + 1) * 132 + r0 + g + 8] = o[nt][3] * inv1;
    }
    __syncthreads();

    float* aob = ao + ((size_t)b * HDIM + (size_t)h * DHEAD) * NSEQ;
    for (int e = tid; e < 64 * 128; e += 256) {
        int d = e >> 7, i = e & 127;
        aob[(size_t)d * NSEQ + i0 + i] = Ts[d * 132 + i];
    }
}

// ---------------------------------------------------------------------------
extern "C" void kernel_launch(void* const* d_in, const int* in_sizes, int n_in,
                              void* d_out, int out_size)
{
    const float* x       = (const float*)d_in[0];
    const float* Wqkv    = (const float*)d_in[1];
    const float* q_scale = (const float*)d_in[2];
    const float* k_scale = (const float*)d_in[3];
    const float* Wout    = (const float*)d_in[4];
    const float* bout    = (const float*)d_in[5];
    float*       out     = (float*)d_out;

    float *qkv = nullptr, *ao = nullptr;
    cudaGetSymbolAddress((void**)&qkv, g_qkv);
    cudaGetSymbolAddress((void**)&ao,  g_ao);

    cudaFuncSetAttribute(attn_tc_kernel,
                         cudaFuncAttributeMaxDynamicSharedMemorySize, ATT_SMEM_BYTES);

    // 1) QKV projection (tf32 mma.sync, 128x128): M=3072, K=512, N=2048
    tf32_gemm_kernel<<<dim3(NSEQ / 128, O3 / 128, BATCH), 256>>>(
        Wqkv, x, qkv, nullptr, O3, CIN, NSEQ);

    // 2) l2-normalize q,k in place (+ learned per-dim scales)
    l2norm_kernel<<<dim3(NSEQ / 256, HEADS, BATCH * 2), 256>>>(
        qkv, q_scale, k_scale);

    // 3) flash attention (tf32 mma.sync, fixed-max softmax, paired frags)
    attn_tc_kernel<<<dim3(NSEQ / 128, HEADS, BATCH), 256, ATT_SMEM_BYTES>>>(qkv, ao);

    // 4) output projection (tf32 mma.sync, 128x128) + bias: M=512, K=1024, N=2048
    tf32_gemm_kernel<<<dim3(NSEQ / 128, CIN / 128, BATCH), 256>>>(
        Wout, ao, out, bout, CIN, HDIM, NSEQ);
}

// round 12
// speedup vs baseline: 1.5221x; 1.4302x over previous
#include <cuda_runtime.h>
#include <cuda_fp16.h>
#include <math.h>
#include <stdint.h>

#define BATCH   2
#define CIN     512
#define NSEQ    2048
#define HEADS   16
#define DHEAD   64
#define HDIM    1024           // HEADS*DHEAD
#define O3      3072           // 3*HDIM
#define ATT_SCALE 8.0f

// Scratch (device globals: allocation-free scratch per harness rules)
__device__ float g_qkv[BATCH * O3 * NSEQ];     // [b][o][n], q/k normalized in place
__device__ float g_ao [BATCH * HDIM * NSEQ];   // attention output [b][c][n]

// ===========================================================================
// helpers (baseline PTX, valid on plain sm_103 — no 'a' features)
// ===========================================================================
__device__ __forceinline__ float to_tf32(float x) {
    uint32_t u;
    asm("cvt.rna.tf32.f32 %0, %1;" : "=r"(u) : "f"(x));
    return __uint_as_float(u);
}
__device__ __forceinline__ uint32_t pack_h2(float lo, float hi) {
    __half2 h = __floats2half2_rn(lo, hi);
    return *(uint32_t*)&h;
}

// tf32: D(16x8) += A(16x8 row) * B(8x8 col)   (proven rounds 5-11)
__device__ __forceinline__ void mma_tf32(float* d, const float4& a, const float2& b) {
    asm volatile(
        "mma.sync.aligned.m16n8k8.row.col.f32.tf32.tf32.f32 "
        "{%0,%1,%2,%3}, {%4,%5,%6,%7}, {%8,%9}, {%0,%1,%2,%3};"
        : "+f"(d[0]), "+f"(d[1]), "+f"(d[2]), "+f"(d[3])
        : "r"(__float_as_uint(a.x)), "r"(__float_as_uint(a.y)),
          "r"(__float_as_uint(a.z)), "r"(__float_as_uint(a.w)),
          "r"(__float_as_uint(b.x)), "r"(__float_as_uint(b.y)));
}

// fp16: D(16x8,f32) += A(16x16 row,f16) * B(16x8 col,f16)
// a = [{A(g,2t),A(g,2t+1)}, {A(g+8,2t),A(g+8,2t+1)},
//      {A(g,2t+8),A(g,2t+9)}, {A(g+8,2t+8),A(g+8,2t+9)}]
// b = [{B(2t,g),B(2t+1,g)}, {B(2t+8,g),B(2t+9,g)}]     g=lane>>2, t=lane&3
// d = [D(g,2t), D(g,2t+1), D(g+8,2t), D(g+8,2t+1)]
__device__ __forceinline__ void mma_f16(float* d, const uint32_t* a,
                                        uint32_t b0, uint32_t b1) {
    asm volatile(
        "mma.sync.aligned.m16n8k16.row.col.f32.f16.f16.f32 "
        "{%0,%1,%2,%3}, {%4,%5,%6,%7}, {%8,%9}, {%0,%1,%2,%3};"
        : "+f"(d[0]), "+f"(d[1]), "+f"(d[2]), "+f"(d[3])
        : "r"(a[0]), "r"(a[1]), "r"(a[2]), "r"(a[3]), "r"(b0), "r"(b1));
}

// ===========================================================================
// tf32 mma.sync GEMM (exact proven 582-config, untouched)
// ===========================================================================
__global__ __launch_bounds__(256, 2)
void tf32_gemm_kernel(const float* __restrict__ W,   // [M][K]
                      const float* __restrict__ X,   // [b][K][N]
                      float* __restrict__ Out,       // [b][M][N]
                      const float* __restrict__ bias,
                      int M, int K, int N)
{
    __shared__ float As[4096];
    __shared__ float Bs[4096];

    const int tid  = threadIdx.x;
    const int wid  = tid >> 5;
    const int lane = tid & 31;
    const int g = lane >> 2;
    const int t = lane & 3;
    const int wm = wid >> 1;
    const int wn = wid & 1;

    const int n0 = blockIdx.x * 128;
    const int m0 = blockIdx.y * 128;
    const int b  = blockIdx.z;

    const float* Ab = W + (size_t)m0 * K;
    const float* Xb = X + (size_t)b * K * N + n0;

    float d[2][8][4];
    #pragma unroll
    for (int a = 0; a < 2; a++)
        #pragma unroll
        for (int j = 0; j < 8; j++)
            #pragma unroll
            for (int r = 0; r < 4; r++) d[a][j][r] = 0.0f;

    const int nch = K >> 5;
    for (int c = 0; c < nch; c++) {
        const int k0 = c << 5;

        #pragma unroll
        for (int i = 0; i < 4; i++) {
            int f  = wid * 4 + i;
            int mt = f >> 2, kt = f & 3;
            const float* ap = Ab + (size_t)(mt * 16 + g) * K + (k0 + kt * 8 + t);
            float4 v;
            v.x = to_tf32(ap[0]);
            v.y = to_tf32(ap[(size_t)8 * K]);
            v.z = to_tf32(ap[4]);
            v.w = to_tf32(ap[(size_t)8 * K + 4]);
            *(float4*)(As + f * 128 + lane * 4) = v;
        }
        #pragma unroll
        for (int i = 0; i < 8; i++) {
            int f  = wid * 8 + i;
            int nt = f >> 2, kt = f & 3;
            const float* bp = Xb + (size_t)(k0 + kt * 8 + t) * N + (nt * 8 + g);
            float2 v;
            v.x = to_tf32(bp[0]);
            v.y = to_tf32(bp[(size_t)4 * N]);
            *(float2*)(Bs + f * 64 + lane * 2) = v;
        }
        __syncthreads();

        const float* Aw = As + (wm * 2) * 4 * 128;
        const float* Bw = Bs + (wn * 8) * 4 * 64;
        #pragma unroll
        for (int kt = 0; kt < 4; kt++) {
            float4 afr[2];
            afr[0] = *(const float4*)(Aw + (kt    ) * 128 + lane * 4);
            afr[1] = *(const float4*)(Aw + (kt + 4) * 128 + lane * 4);
            float2 bfr[8];
            #pragma unroll
            for (int j = 0; j < 8; j++)
                bfr[j] = *(const float2*)(Bw + (j * 4 + kt) * 64 + lane * 2);
            #pragma unroll
            for (int a = 0; a < 2; a++)
                #pragma unroll
                for (int j = 0; j < 8; j++)
                    mma_tf32(d[a][j], afr[a], bfr[j]);
        }
        __syncthreads();
    }

    float* Ob = Out + (size_t)b * M * N;
    #pragma unroll
    for (int a = 0; a < 2; a++) {
        const int row = m0 + wm * 32 + a * 16 + g;
        const float b1 = bias ? bias[row]     : 0.0f;
        const float b2 = bias ? bias[row + 8] : 0.0f;
        #pragma unroll
        for (int j = 0; j < 8; j++) {
            const int col = n0 + wn * 64 + j * 8 + t * 2;
            float2 v0; v0.x = d[a][j][0] + b1; v0.y = d[a][j][1] + b1;
            float2 v1; v1.x = d[a][j][2] + b2; v1.y = d[a][j][3] + b2;
            *(float2*)(Ob + (size_t)row * N + col)       = v0;
            *(float2*)(Ob + (size_t)(row + 8) * N + col) = v1;
        }
    }
}

// ---------------------------------------------------------------------------
// L2 normalization of q,k over head-dim (in place in g_qkv), applying scales.
// ---------------------------------------------------------------------------
__global__ __launch_bounds__(256)
void l2norm_kernel(float* __restrict__ qkv,
                   const float* __restrict__ qs,
                   const float* __restrict__ ks)
{
    const int n  = blockIdx.x * 256 + threadIdx.x;
    const int h  = blockIdx.y;
    const int bw = blockIdx.z;
    const int b  = bw >> 1;
    const int w  = bw & 1;
    const float* sc = w ? ks : qs;

    float* base = qkv + ((size_t)b * O3 + (size_t)w * HDIM + (size_t)h * DHEAD) * NSEQ + n;

    float ss = 0.0f;
    #pragma unroll
    for (int d = 0; d < DHEAD; d++) {
        float v = base[(size_t)d * NSEQ];
        ss += v * v;
    }
    float inv = 1.0f / fmaxf(sqrtf(ss), 1e-12f);
    #pragma unroll
    for (int d = 0; d < DHEAD; d++) {
        base[(size_t)d * NSEQ] = base[(size_t)d * NSEQ] * inv * sc[d];
    }
}

// ===========================================================================
// Flash attention v5: fp16 m16n8k16 mma.sync, fixed-shift softmax,
// REGISTER-DIRECT P (S-MMA D-fragments == PV A-fragments; no P smem).
// Cosine attention: logits in [-8,8]; P' = exp(s + 1) in [8e-4, 9e3] — all
// fp16-normal; the shift cancels in O/l.
// One CTA = 128 query rows of one (b,h); 8 warps; warp w owns rows w*16..+15.
// Smem: Kf/Vf = 32 B-frags each, one uint2 per lane per frag (8KB each);
//       epilogue reuses smem for the 64x132 O^T transpose buffer.
// Pipeline: STS K; sync; LDG V; S-MMA+softmax(reg); STS V; sync;
//           LDG K(next); PV-MMA.
// ===========================================================================
#define ATT_SMEM_BYTES (64 * 132 * 4)     // 33792 >= 16KB staging

__global__ __launch_bounds__(256, 2)
void attn_f16_kernel(const float* __restrict__ qkv, float* __restrict__ ao)
{
    extern __shared__ char smc[];
    uint2* Kf = (uint2*)smc;          // 32 frags * 32 lanes (8KB)
    uint2* Vf = Kf + 1024;            // 8KB
    float* Ts = (float*)smc;          // epilogue reuse (64 x 132)

    const int tid  = threadIdx.x;
    const int wid  = tid >> 5;
    const int lane = tid & 31;
    const int g = lane >> 2;
    const int t = lane & 3;
    const int r0 = wid * 16;

    const int i0 = blockIdx.x * 128;
    const int h  = blockIdx.y;
    const int b  = blockIdx.z;

    const float* qb = qkv + ((size_t)b * O3 + (size_t)h * DHEAD) * NSEQ;
    const float* kb = qb + (size_t)HDIM * NSEQ;
    const float* vb = qb + (size_t)(2 * HDIM) * NSEQ;

    // ---- Q A-fragments (fp16), live whole kernel: 4 k16-chunks x 4 regs
    uint32_t qf[4][4];
    {
        const int col = i0 + r0 + g;
        #pragma unroll
        for (int kc = 0; kc < 4; kc++) {
            const float* q0 = qb + (size_t)(kc * 16 + 2 * t) * NSEQ + col;
            const float* q1 = q0 + NSEQ;
            qf[kc][0] = pack_h2(q0[0] * ATT_SCALE, q1[0] * ATT_SCALE);
            qf[kc][1] = pack_h2(q0[8] * ATT_SCALE, q1[8] * ATT_SCALE);
            qf[kc][2] = pack_h2(q0[(size_t)8 * NSEQ] * ATT_SCALE,
                                q1[(size_t)8 * NSEQ] * ATT_SCALE);
            qf[kc][3] = pack_h2(q0[(size_t)8 * NSEQ + 8] * ATT_SCALE,
                                q1[(size_t)8 * NSEQ + 8] * ATT_SCALE);
        }
    }

    // ---- preload K tile 0 (warp w stages frags nt=w, kc=0..3)
    float kreg[4][4];
    #pragma unroll
    for (int kc = 0; kc < 4; kc++) {
        const float* kp = kb + (size_t)(kc * 16 + 2 * t) * NSEQ + wid * 8 + g;
        kreg[kc][0] = kp[0];
        kreg[kc][1] = kp[NSEQ];
        kreg[kc][2] = kp[(size_t)8 * NSEQ];
        kreg[kc][3] = kp[(size_t)9 * NSEQ];
    }

    float lp0 = 0.0f, lp1 = 0.0f;     // per-lane partial row sums (reduce at end)
    float o[8][4];
    #pragma unroll
    for (int dt = 0; dt < 8; dt++)
        #pragma unroll
        for (int r = 0; r < 4; r++) o[dt][r] = 0.0f;

    for (int j0 = 0; j0 < NSEQ; j0 += 64) {
        // ---- publish K frags (safe: all warps passed prior V-sync => done S-MMA)
        #pragma unroll
        for (int kc = 0; kc < 4; kc++) {
            uint2 u;
            u.x = pack_h2(kreg[kc][0], kreg[kc][1]);
            u.y = pack_h2(kreg[kc][2], kreg[kc][3]);
            Kf[(wid * 4 + kc) * 32 + lane] = u;
        }
        __syncthreads();

        // ---- issue V loads (covered by S-MMA + softmax)
        float2 vreg[4][2];
        #pragma unroll
        for (int kc = 0; kc < 4; kc++) {
            const float* vp = vb + (size_t)(wid * 8 + g) * NSEQ + j0 + kc * 16 + 2 * t;
            vreg[kc][0] = *(const float2*)vp;
            vreg[kc][1] = *(const float2*)(vp + 8);
        }

        // ---- S = Q K^T : 32 fp16 MMAs
        float s[8][4];
        #pragma unroll
        for (int nt = 0; nt < 8; nt++)
            #pragma unroll
            for (int r = 0; r < 4; r++) s[nt][r] = 0.0f;

        #pragma unroll
        for (int kc = 0; kc < 4; kc++)
            #pragma unroll
            for (int nt = 0; nt < 8; nt++) {
                uint2 kb2 = Kf[(nt * 4 + kc) * 32 + lane];
                mma_f16(s[nt], qf[kc], kb2.x, kb2.y);
            }

        // ---- fixed-shift softmax, register-resident P' = exp(s + 1)
        #pragma unroll
        for (int nt = 0; nt < 8; nt++) {
            s[nt][0] = __expf(s[nt][0] + 1.0f);
            s[nt][1] = __expf(s[nt][1] + 1.0f);
            s[nt][2] = __expf(s[nt][2] + 1.0f);
            s[nt][3] = __expf(s[nt][3] + 1.0f);
            lp0 += s[nt][0] + s[nt][1];
            lp1 += s[nt][2] + s[nt][3];
        }
        // D-fragment pairs (nt=2kc, 2kc+1) ARE the PV A-fragment for chunk kc
        uint32_t pa[4][4];
        #pragma unroll
        for (int kc = 0; kc < 4; kc++) {
            pa[kc][0] = pack_h2(s[2 * kc][0],     s[2 * kc][1]);
            pa[kc][1] = pack_h2(s[2 * kc][2],     s[2 * kc][3]);
            pa[kc][2] = pack_h2(s[2 * kc + 1][0], s[2 * kc + 1][1]);
            pa[kc][3] = pack_h2(s[2 * kc + 1][2], s[2 * kc + 1][3]);
        }

        // ---- publish V frags (safe: all warps passed K-sync => done prior PV)
        #pragma unroll
        for (int kc = 0; kc < 4; kc++) {
            uint2 u;
            u.x = pack_h2(vreg[kc][0].x, vreg[kc][0].y);
            u.y = pack_h2(vreg[kc][1].x, vreg[kc][1].y);
            Vf[(wid * 4 + kc) * 32 + lane] = u;
        }
        __syncthreads();

        // ---- prefetch next K tile (covered by PV)
        const int jn = (j0 + 64 < NSEQ) ? j0 + 64 : 0;
        #pragma unroll
        for (int kc = 0; kc < 4; kc++) {
            const float* kp = kb + (size_t)(kc * 16 + 2 * t) * NSEQ + jn + wid * 8 + g;
            kreg[kc][0] = kp[0];
            kreg[kc][1] = kp[NSEQ];
            kreg[kc][2] = kp[(size_t)8 * NSEQ];
            kreg[kc][3] = kp[(size_t)9 * NSEQ];
        }

        // ---- O += P' V^T : 32 fp16 MMAs, A straight from registers
        #pragma unroll
        for (int kc = 0; kc < 4; kc++)
            #pragma unroll
            for (int dt = 0; dt < 8; dt++) {
                uint2 vb2 = Vf[(dt * 4 + kc) * 32 + lane];
                mma_f16(o[dt], pa[kc], vb2.x, vb2.y);
            }
    }

    // ---- finalize row sums (single reduction, deferred out of the loop)
    lp0 += __shfl_xor_sync(0xffffffffu, lp0, 1);
    lp0 += __shfl_xor_sync(0xffffffffu, lp0, 2);
    lp1 += __shfl_xor_sync(0xffffffffu, lp1, 1);
    lp1 += __shfl_xor_sync(0xffffffffu, lp1, 2);
    const float inv0 = 1.0f / lp0;
    const float inv1 = 1.0f / lp1;

    __syncthreads();   // staging buffers dead; reuse smem for transpose

    #pragma unroll
    for (int dt = 0; dt < 8; dt++) {
        Ts[(dt * 8 + 2 * t)     * 132 + r0 + g]     = o[dt][0] * inv0;
        Ts[(dt * 8 + 2 * t + 1) * 132 + r0 + g]     = o[dt][1] * inv0;
        Ts[(dt * 8 + 2 * t)     * 132 + r0 + g + 8] = o[dt][2] * inv1;
        Ts[(dt * 8 + 2 * t + 1) * 132 + r0 + g + 8] = o[dt][3] * inv1;
    }
    __syncthreads();

    float* aob = ao + ((size_t)b * HDIM + (size_t)h * DHEAD) * NSEQ;
    for (int e = tid; e < 64 * 128; e += 256) {
        int d = e >> 7, i = e & 127;
        aob[(size_t)d * NSEQ + i0 + i] = Ts[d * 132 + i];
    }
}

// ---------------------------------------------------------------------------
extern "C" void kernel_launch(void* const* d_in, const int* in_sizes, int n_in,
                              void* d_out, int out_size)
{
    const float* x       = (const float*)d_in[0];
    const float* Wqkv    = (const float*)d_in[1];
    const float* q_scale = (const float*)d_in[2];
    const float* k_scale = (const float*)d_in[3];
    const float* Wout    = (const float*)d_in[4];
    const float* bout    = (const float*)d_in[5];
    float*       out     = (float*)d_out;

    float *qkv = nullptr, *ao = nullptr;
    cudaGetSymbolAddress((void**)&qkv, g_qkv);
    cudaGetSymbolAddress((void**)&ao,  g_ao);

    cudaFuncSetAttribute(attn_f16_kernel,
                         cudaFuncAttributeMaxDynamicSharedMemorySize, ATT_SMEM_BYTES);

    // 1) QKV projection (tf32 mma.sync, 128x128): M=3072, K=512, N=2048
    tf32_gemm_kernel<<<dim3(NSEQ / 128, O3 / 128, BATCH), 256>>>(
        Wqkv, x, qkv, nullptr, O3, CIN, NSEQ);

    // 2) l2-normalize q,k in place (+ learned per-dim scales)
    l2norm_kernel<<<dim3(NSEQ / 256, HEADS, BATCH * 2), 256>>>(
        qkv, q_scale, k_scale);

    // 3) flash attention (fp16 mma.sync, register-direct P)
    attn_f16_kernel<<<dim3(NSEQ / 128, HEADS, BATCH), 256, ATT_SMEM_BYTES>>>(qkv, ao);

    // 4) output projection (tf32 mma.sync, 128x128) + bias: M=512, K=1024, N=2048
    tf32_gemm_kernel<<<dim3(NSEQ / 128, CIN / 128, BATCH), 256>>>(
        Wout, ao, out, bout, CIN, HDIM, NSEQ);
}

// round 13
// speedup vs baseline: 1.8132x; 1.1912x over previous
#include <cuda_runtime.h>
#include <cuda_fp16.h>
#include <math.h>
#include <stdint.h>

#define BATCH   2
#define CIN     512
#define NSEQ    2048
#define HEADS   16
#define DHEAD   64
#define HDIM    1024           // HEADS*DHEAD
#define O3      3072           // 3*HDIM
#define ATT_SCALE 8.0f

// Scratch (device globals: allocation-free scratch per harness rules)
__device__ float g_qkv[BATCH * O3 * NSEQ];     // [b][o][n], q/k normalized in place
__device__ float g_ao [BATCH * HDIM * NSEQ];   // attention output [b][c][n]

// ===========================================================================
// helpers (baseline PTX, valid on plain sm_103 — no 'a' features)
// ===========================================================================
__device__ __forceinline__ uint32_t pack_h2(float lo, float hi) {
    __half2 h = __floats2half2_rn(lo, hi);
    return *(uint32_t*)&h;
}

// fp16: D(16x8,f32) += A(16x16 row,f16) * B(16x8 col,f16)
// a = [{A(g,2t),A(g,2t+1)}, {A(g+8,2t),A(g+8,2t+1)},
//      {A(g,2t+8),A(g,2t+9)}, {A(g+8,2t+8),A(g+8,2t+9)}]
// b = [{B(2t,g),B(2t+1,g)}, {B(2t+8,g),B(2t+9,g)}]     g=lane>>2, t=lane&3
// d = [D(g,2t), D(g,2t+1), D(g+8,2t), D(g+8,2t+1)]
// (mapping proven by round-12 attention kernel)
__device__ __forceinline__ void mma_f16(float* d, const uint32_t* a,
                                        uint32_t b0, uint32_t b1) {
    asm volatile(
        "mma.sync.aligned.m16n8k16.row.col.f32.f16.f16.f32 "
        "{%0,%1,%2,%3}, {%4,%5,%6,%7}, {%8,%9}, {%0,%1,%2,%3};"
        : "+f"(d[0]), "+f"(d[1]), "+f"(d[2]), "+f"(d[3])
        : "r"(a[0]), "r"(a[1]), "r"(a[2]), "r"(a[3]), "r"(b0), "r"(b1));
}

// ===========================================================================
// fp16 mma.sync GEMM: Out[b][m][n] = sum_k W[m][k] * X[b][k][n] (+ bias[m])
// CTA tile 128m x 128n, 8 warps as 4(m) x 2(n), warp tile 32m x 64n.
// K-chunk 32 (= 2 k16 steps). Fragment-permuted fp16 smem:
//   A frag f = mt*2+kc : 128 uint32, lane*4 -> one LDS.128 = full A-operand.
//   B frag f = nt*2+kc :  64 uint32, lane*2 -> one LDS.64  = full B-operand.
// Same proven structure as the tf32 GEMM (rounds 5-12), half the work.
// ===========================================================================
__global__ __launch_bounds__(256, 2)
void f16_gemm_kernel(const float* __restrict__ W,   // [M][K]
                     const float* __restrict__ X,   // [b][K][N]
                     float* __restrict__ Out,       // [b][M][N]
                     const float* __restrict__ bias,
                     int M, int K, int N)
{
    __shared__ uint32_t Af[2048];   // 16 A-frags * 128
    __shared__ uint32_t Bf[2048];   // 32 B-frags * 64

    const int tid  = threadIdx.x;
    const int wid  = tid >> 5;
    const int lane = tid & 31;
    const int g = lane >> 2;
    const int t = lane & 3;
    const int wm = wid >> 1;
    const int wn = wid & 1;

    const int n0 = blockIdx.x * 128;
    const int m0 = blockIdx.y * 128;
    const int b  = blockIdx.z;

    const float* Ab = W + (size_t)m0 * K;
    const float* Xb = X + (size_t)b * K * N + n0;

    float d[2][8][4];
    #pragma unroll
    for (int a = 0; a < 2; a++)
        #pragma unroll
        for (int j = 0; j < 8; j++)
            #pragma unroll
            for (int r = 0; r < 4; r++) d[a][j][r] = 0.0f;

    const int nch = K >> 5;
    for (int c = 0; c < nch; c++) {
        const int k0 = c << 5;

        // ---- stage A: warp w fills frags (mt=w, kc=0,1); 4 LDG.64 + STS.128
        #pragma unroll
        for (int kc = 0; kc < 2; kc++) {
            const float* ap = Ab + (size_t)(wid * 16 + g) * K + (k0 + kc * 16 + 2 * t);
            float2 q0 = *(const float2*)ap;
            float2 q1 = *(const float2*)(ap + (size_t)8 * K);
            float2 q2 = *(const float2*)(ap + 8);
            float2 q3 = *(const float2*)(ap + (size_t)8 * K + 8);
            uint4 u;
            u.x = pack_h2(q0.x, q0.y);
            u.y = pack_h2(q1.x, q1.y);
            u.z = pack_h2(q2.x, q2.y);
            u.w = pack_h2(q3.x, q3.y);
            *(uint4*)(Af + (wid * 2 + kc) * 128 + lane * 4) = u;
        }
        // ---- stage B: warp w fills frags (nt=2w..2w+1, kc=0,1); 4 LDG.32 + STS.64
        #pragma unroll
        for (int i = 0; i < 4; i++) {
            const int nt = wid * 2 + (i >> 1);
            const int kc = i & 1;
            const float* bp = Xb + (size_t)(k0 + kc * 16 + 2 * t) * N + (nt * 8 + g);
            float b00 = bp[0];
            float b01 = bp[N];
            float b10 = bp[(size_t)8 * N];
            float b11 = bp[(size_t)9 * N];
            uint2 u;
            u.x = pack_h2(b00, b01);
            u.y = pack_h2(b10, b11);
            *(uint2*)(Bf + (nt * 2 + kc) * 64 + lane * 2) = u;
        }
        __syncthreads();

        // ---- compute: 2 k16 steps, 2x8 mma tiles per warp per step
        #pragma unroll
        for (int kc = 0; kc < 2; kc++) {
            uint4 a0 = *(const uint4*)(Af + ((wm * 2    ) * 2 + kc) * 128 + lane * 4);
            uint4 a1 = *(const uint4*)(Af + ((wm * 2 + 1) * 2 + kc) * 128 + lane * 4);
            #pragma unroll
            for (int j = 0; j < 8; j++) {
                uint2 bb = *(const uint2*)(Bf + ((wn * 8 + j) * 2 + kc) * 64 + lane * 2);
                mma_f16(d[0][j], (const uint32_t*)&a0, bb.x, bb.y);
                mma_f16(d[1][j], (const uint32_t*)&a1, bb.x, bb.y);
            }
        }
        __syncthreads();
    }

    // ---- epilogue: coalesced float2 stores (+bias), same as proven kernel
    float* Ob = Out + (size_t)b * M * N;
    #pragma unroll
    for (int a = 0; a < 2; a++) {
        const int row = m0 + wm * 32 + a * 16 + g;
        const float b1 = bias ? bias[row]     : 0.0f;
        const float b2 = bias ? bias[row + 8] : 0.0f;
        #pragma unroll
        for (int j = 0; j < 8; j++) {
            const int col = n0 + wn * 64 + j * 8 + t * 2;
            float2 v0; v0.x = d[a][j][0] + b1; v0.y = d[a][j][1] + b1;
            float2 v1; v1.x = d[a][j][2] + b2; v1.y = d[a][j][3] + b2;
            *(float2*)(Ob + (size_t)row * N + col)       = v0;
            *(float2*)(Ob + (size_t)(row + 8) * N + col) = v1;
        }
    }
}

// ---------------------------------------------------------------------------
// L2 normalization of q,k over head-dim (in place in g_qkv), applying scales.
// ---------------------------------------------------------------------------
__global__ __launch_bounds__(256)
void l2norm_kernel(float* __restrict__ qkv,
                   const float* __restrict__ qs,
                   const float* __restrict__ ks)
{
    const int n  = blockIdx.x * 256 + threadIdx.x;
    const int h  = blockIdx.y;
    const int bw = blockIdx.z;
    const int b  = bw >> 1;
    const int w  = bw & 1;
    const float* sc = w ? ks : qs;

    float* base = qkv + ((size_t)b * O3 + (size_t)w * HDIM + (size_t)h * DHEAD) * NSEQ + n;

    float ss = 0.0f;
    #pragma unroll
    for (int d = 0; d < DHEAD; d++) {
        float v = base[(size_t)d * NSEQ];
        ss += v * v;
    }
    float inv = 1.0f / fmaxf(sqrtf(ss), 1e-12f);
    #pragma unroll
    for (int d = 0; d < DHEAD; d++) {
        base[(size_t)d * NSEQ] = base[(size_t)d * NSEQ] * inv * sc[d];
    }
}

// ===========================================================================
// Flash attention v5 (round-12 proven, unchanged): fp16 m16n8k16,
// fixed-shift softmax P' = exp(s+1), register-direct P.
// ===========================================================================
#define ATT_SMEM_BYTES (64 * 132 * 4)

__global__ __launch_bounds__(256, 2)
void attn_f16_kernel(const float* __restrict__ qkv, float* __restrict__ ao)
{
    extern __shared__ char smc[];
    uint2* Kf = (uint2*)smc;          // 32 frags * 32 lanes (8KB)
    uint2* Vf = Kf + 1024;            // 8KB
    float* Ts = (float*)smc;          // epilogue reuse (64 x 132)

    const int tid  = threadIdx.x;
    const int wid  = tid >> 5;
    const int lane = tid & 31;
    const int g = lane >> 2;
    const int t = lane & 3;
    const int r0 = wid * 16;

    const int i0 = blockIdx.x * 128;
    const int h  = blockIdx.y;
    const int b  = blockIdx.z;

    const float* qb = qkv + ((size_t)b * O3 + (size_t)h * DHEAD) * NSEQ;
    const float* kb = qb + (size_t)HDIM * NSEQ;
    const float* vb = qb + (size_t)(2 * HDIM) * NSEQ;

    // ---- Q A-fragments (fp16), live whole kernel
    uint32_t qf[4][4];
    {
        const int col = i0 + r0 + g;
        #pragma unroll
        for (int kc = 0; kc < 4; kc++) {
            const float* q0 = qb + (size_t)(kc * 16 + 2 * t) * NSEQ + col;
            const float* q1 = q0 + NSEQ;
            qf[kc][0] = pack_h2(q0[0] * ATT_SCALE, q1[0] * ATT_SCALE);
            qf[kc][1] = pack_h2(q0[8] * ATT_SCALE, q1[8] * ATT_SCALE);
            qf[kc][2] = pack_h2(q0[(size_t)8 * NSEQ] * ATT_SCALE,
                                q1[(size_t)8 * NSEQ] * ATT_SCALE);
            qf[kc][3] = pack_h2(q0[(size_t)8 * NSEQ + 8] * ATT_SCALE,
                                q1[(size_t)8 * NSEQ + 8] * ATT_SCALE);
        }
    }

    // ---- preload K tile 0 (warp w stages frags nt=w, kc=0..3)
    float kreg[4][4];
    #pragma unroll
    for (int kc = 0; kc < 4; kc++) {
        const float* kp = kb + (size_t)(kc * 16 + 2 * t) * NSEQ + wid * 8 + g;
        kreg[kc][0] = kp[0];
        kreg[kc][1] = kp[NSEQ];
        kreg[kc][2] = kp[(size_t)8 * NSEQ];
        kreg[kc][3] = kp[(size_t)9 * NSEQ];
    }

    float lp0 = 0.0f, lp1 = 0.0f;
    float o[8][4];
    #pragma unroll
    for (int dt = 0; dt < 8; dt++)
        #pragma unroll
        for (int r = 0; r < 4; r++) o[dt][r] = 0.0f;

    for (int j0 = 0; j0 < NSEQ; j0 += 64) {
        #pragma unroll
        for (int kc = 0; kc < 4; kc++) {
            uint2 u;
            u.x = pack_h2(kreg[kc][0], kreg[kc][1]);
            u.y = pack_h2(kreg[kc][2], kreg[kc][3]);
            Kf[(wid * 4 + kc) * 32 + lane] = u;
        }
        __syncthreads();

        float2 vreg[4][2];
        #pragma unroll
        for (int kc = 0; kc < 4; kc++) {
            const float* vp = vb + (size_t)(wid * 8 + g) * NSEQ + j0 + kc * 16 + 2 * t;
            vreg[kc][0] = *(const float2*)vp;
            vreg[kc][1] = *(const float2*)(vp + 8);
        }

        float s[8][4];
        #pragma unroll
        for (int nt = 0; nt < 8; nt++)
            #pragma unroll
            for (int r = 0; r < 4; r++) s[nt][r] = 0.0f;

        #pragma unroll
        for (int kc = 0; kc < 4; kc++)
            #pragma unroll
            for (int nt = 0; nt < 8; nt++) {
                uint2 kb2 = Kf[(nt * 4 + kc) * 32 + lane];
                mma_f16(s[nt], qf[kc], kb2.x, kb2.y);
            }

        #pragma unroll
        for (int nt = 0; nt < 8; nt++) {
            s[nt][0] = __expf(s[nt][0] + 1.0f);
            s[nt][1] = __expf(s[nt][1] + 1.0f);
            s[nt][2] = __expf(s[nt][2] + 1.0f);
            s[nt][3] = __expf(s[nt][3] + 1.0f);
            lp0 += s[nt][0] + s[nt][1];
            lp1 += s[nt][2] + s[nt][3];
        }
        uint32_t pa[4][4];
        #pragma unroll
        for (int kc = 0; kc < 4; kc++) {
            pa[kc][0] = pack_h2(s[2 * kc][0],     s[2 * kc][1]);
            pa[kc][1] = pack_h2(s[2 * kc][2],     s[2 * kc][3]);
            pa[kc][2] = pack_h2(s[2 * kc + 1][0], s[2 * kc + 1][1]);
            pa[kc][3] = pack_h2(s[2 * kc + 1][2], s[2 * kc + 1][3]);
        }

        #pragma unroll
        for (int kc = 0; kc < 4; kc++) {
            uint2 u;
            u.x = pack_h2(vreg[kc][0].x, vreg[kc][0].y);
            u.y = pack_h2(vreg[kc][1].x, vreg[kc][1].y);
            Vf[(wid * 4 + kc) * 32 + lane] = u;
        }
        __syncthreads();

        const int jn = (j0 + 64 < NSEQ) ? j0 + 64 : 0;
        #pragma unroll
        for (int kc = 0; kc < 4; kc++) {
            const float* kp = kb + (size_t)(kc * 16 + 2 * t) * NSEQ + jn + wid * 8 + g;
            kreg[kc][0] = kp[0];
            kreg[kc][1] = kp[NSEQ];
            kreg[kc][2] = kp[(size_t)8 * NSEQ];
            kreg[kc][3] = kp[(size_t)9 * NSEQ];
        }

        #pragma unroll
        for (int kc = 0; kc < 4; kc++)
            #pragma unroll
            for (int dt = 0; dt < 8; dt++) {
                uint2 vb2 = Vf[(dt * 4 + kc) * 32 + lane];
                mma_f16(o[dt], pa[kc], vb2.x, vb2.y);
            }
    }

    lp0 += __shfl_xor_sync(0xffffffffu, lp0, 1);
    lp0 += __shfl_xor_sync(0xffffffffu, lp0, 2);
    lp1 += __shfl_xor_sync(0xffffffffu, lp1, 1);
    lp1 += __shfl_xor_sync(0xffffffffu, lp1, 2);
    const float inv0 = 1.0f / lp0;
    const float inv1 = 1.0f / lp1;

    __syncthreads();

    #pragma unroll
    for (int dt = 0; dt < 8; dt++) {
        Ts[(dt * 8 + 2 * t)     * 132 + r0 + g]     = o[dt][0] * inv0;
        Ts[(dt * 8 + 2 * t + 1) * 132 + r0 + g]     = o[dt][1] * inv0;
        Ts[(dt * 8 + 2 * t)     * 132 + r0 + g + 8] = o[dt][2] * inv1;
        Ts[(dt * 8 + 2 * t + 1) * 132 + r0 + g + 8] = o[dt][3] * inv1;
    }
    __syncthreads();

    float* aob = ao + ((size_t)b * HDIM + (size_t)h * DHEAD) * NSEQ;
    for (int e = tid; e < 64 * 128; e += 256) {
        int d = e >> 7, i = e & 127;
        aob[(size_t)d * NSEQ + i0 + i] = Ts[d * 132 + i];
    }
}

// ---------------------------------------------------------------------------
extern "C" void kernel_launch(void* const* d_in, const int* in_sizes, int n_in,
                              void* d_out, int out_size)
{
    const float* x       = (const float*)d_in[0];
    const float* Wqkv    = (const float*)d_in[1];
    const float* q_scale = (const float*)d_in[2];
    const float* k_scale = (const float*)d_in[3];
    const float* Wout    = (const float*)d_in[4];
    const float* bout    = (const float*)d_in[5];
    float*       out     = (float*)d_out;

    float *qkv = nullptr, *ao = nullptr;
    cudaGetSymbolAddress((void**)&qkv, g_qkv);
    cudaGetSymbolAddress((void**)&ao,  g_ao);

    cudaFuncSetAttribute(attn_f16_kernel,
                         cudaFuncAttributeMaxDynamicSharedMemorySize, ATT_SMEM_BYTES);

    // 1) QKV projection (fp16 mma.sync, 128x128): M=3072, K=512, N=2048
    f16_gemm_kernel<<<dim3(NSEQ / 128, O3 / 128, BATCH), 256>>>(
        Wqkv, x, qkv, nullptr, O3, CIN, NSEQ);

    // 2) l2-normalize q,k in place (+ learned per-dim scales)
    l2norm_kernel<<<dim3(NSEQ / 256, HEADS, BATCH * 2), 256>>>(
        qkv, q_scale, k_scale);

    // 3) flash attention (fp16 mma.sync, register-direct P)
    attn_f16_kernel<<<dim3(NSEQ / 128, HEADS, BATCH), 256, ATT_SMEM_BYTES>>>(qkv, ao);

    // 4) output projection (fp16 mma.sync, 128x128) + bias: M=512, K=1024, N=2048
    f16_gemm_kernel<<<dim3(NSEQ / 128, CIN / 128, BATCH), 256>>>(
        Wout, ao, out, bout, CIN, HDIM, NSEQ);
}